// round 16
// baseline (speedup 1.0000x reference)
#include <cuda_runtime.h>
#include <cstdint>

#define Bb 8
#define Nn 2048
#define Mm 256
#define Qq 16384
#define Dd 32
#define Rr 16
#define Kk 16
#define Hh 64
#define LAM 5.0f
#define NITER 20
#define RAD 0.005859375f   // 1.5/256 exact in binary

// ---------------- scratch (device globals; no allocation allowed) ----------
__device__ float g_c0[Bb*Mm*Dd];     // c_loc only; gvec added inside cg
__device__ float g_c [Bb*Mm*Dd];

__device__ __forceinline__ float warp_sum(float v) {
#pragma unroll
    for (int o = 16; o; o >>= 1) v += __shfl_xor_sync(0xffffffffu, v, o);
    return v;
}

__device__ __forceinline__ unsigned smem_u32(const void* p) {
    unsigned a;
    asm("{ .reg .u64 t; cvta.to.shared.u64 t, %1; cvt.u32.u64 %0, t; }"
        : "=r"(a) : "l"(p));
    return a;
}

// store 4 bytes into peer CTA (rank) smem at the address corresponding to laddr
__device__ __forceinline__ void st_remote(unsigned laddr, unsigned rank, float v) {
    unsigned r;
    asm volatile("mapa.shared::cluster.u32 %0, %1, %2;" : "=r"(r) : "r"(laddr), "r"(rank));
    asm volatile("st.shared::cluster.f32 [%0], %1;" :: "r"(r), "f"(v) : "memory");
}

__device__ __forceinline__ void cluster_sync_() {
    asm volatile("barrier.cluster.arrive.aligned;" ::: "memory");  // release
    asm volatile("barrier.cluster.wait.aligned;"   ::: "memory");  // acquire
}

// ---------------- kernel 1: encoder, 4x4 register-tiled h2 GEMM -------------
__global__ __launch_bounds__(64) void enc_kernel(
    const float* __restrict__ xs, const float* __restrict__ us,
    const float* __restrict__ centers, const int* __restrict__ idx,
    const float* __restrict__ W1, const float* __restrict__ b1,
    const float* __restrict__ W2, const float* __restrict__ b2,
    const float* __restrict__ W3, const float* __restrict__ b3)
{
    __shared__ float sW2[64*64];    // row-major [i][j], 16 KB, no transpose
    __shared__ float sh1[16*68];    // h1[k][i], float4-aligned rows
    __shared__ float srel[16], su[16], sW1[128];
    __shared__ float spart[4][64];  // per-kq relu-sums over k
    __shared__ float shbar[64];
    int m = blockIdx.x, b = blockIdx.y, t = threadIdx.x;

    // coop load W2 (coalesced float4, direct store: conflict-free)
    for (int i4 = t; i4 < 1024; i4 += 64)
        ((float4*)sW2)[i4] = ((const float4*)W2)[i4];
    for (int i = t; i < 128; i += 64) sW1[i] = W1[i];
    if (t < 16) {
        int sidx = idx[m*Kk + t];
        srel[t] = (xs[b*Nn + sidx] - centers[m]) / RAD;
        su[t]   = us[b*Nn + sidx];
    }
    __syncthreads();

    {   // h1: thread t = hidden unit i
        float wa = sW1[t], wb = sW1[64+t], bb = b1[t];
#pragma unroll
        for (int k = 0; k < 16; k++)
            sh1[k*68 + t] = fmaxf(fmaf(srel[k], wa, fmaf(su[k], wb, bb)), 0.f);
    }
    __syncthreads();

    {   // h2 = relu(h1 @ W2 + b2), 4k x 4j register tile per thread
        int jq = t & 15, kq = t >> 4;
        int j0 = jq * 4, k0 = kq * 4;
        float acc[4][4];
#pragma unroll
        for (int jj = 0; jj < 4; jj++) {
            float bv = b2[j0 + jj];
#pragma unroll
            for (int kk = 0; kk < 4; kk++) acc[kk][jj] = bv;
        }
#pragma unroll 4
        for (int i = 0; i < 64; i += 4) {
            float4 a0 = *(const float4*)&sh1[(k0+0)*68 + i];
            float4 a1 = *(const float4*)&sh1[(k0+1)*68 + i];
            float4 a2 = *(const float4*)&sh1[(k0+2)*68 + i];
            float4 a3 = *(const float4*)&sh1[(k0+3)*68 + i];
            float4 b0 = *(const float4*)&sW2[(i+0)*64 + j0];
            float4 b1v = *(const float4*)&sW2[(i+1)*64 + j0];
            float4 b2v = *(const float4*)&sW2[(i+2)*64 + j0];
            float4 b3v = *(const float4*)&sW2[(i+3)*64 + j0];
#define ENC_STEP(av, bv) \
            acc[0][0] = fmaf(av.x, bv.x, acc[0][0]); /* placeholder */
            // ii = 0
            acc[0][0]=fmaf(a0.x,b0.x,acc[0][0]); acc[0][1]=fmaf(a0.x,b0.y,acc[0][1]);
            acc[0][2]=fmaf(a0.x,b0.z,acc[0][2]); acc[0][3]=fmaf(a0.x,b0.w,acc[0][3]);
            acc[1][0]=fmaf(a1.x,b0.x,acc[1][0]); acc[1][1]=fmaf(a1.x,b0.y,acc[1][1]);
            acc[1][2]=fmaf(a1.x,b0.z,acc[1][2]); acc[1][3]=fmaf(a1.x,b0.w,acc[1][3]);
            acc[2][0]=fmaf(a2.x,b0.x,acc[2][0]); acc[2][1]=fmaf(a2.x,b0.y,acc[2][1]);
            acc[2][2]=fmaf(a2.x,b0.z,acc[2][2]); acc[2][3]=fmaf(a2.x,b0.w,acc[2][3]);
            acc[3][0]=fmaf(a3.x,b0.x,acc[3][0]); acc[3][1]=fmaf(a3.x,b0.y,acc[3][1]);
            acc[3][2]=fmaf(a3.x,b0.z,acc[3][2]); acc[3][3]=fmaf(a3.x,b0.w,acc[3][3]);
            // ii = 1
            acc[0][0]=fmaf(a0.y,b1v.x,acc[0][0]); acc[0][1]=fmaf(a0.y,b1v.y,acc[0][1]);
            acc[0][2]=fmaf(a0.y,b1v.z,acc[0][2]); acc[0][3]=fmaf(a0.y,b1v.w,acc[0][3]);
            acc[1][0]=fmaf(a1.y,b1v.x,acc[1][0]); acc[1][1]=fmaf(a1.y,b1v.y,acc[1][1]);
            acc[1][2]=fmaf(a1.y,b1v.z,acc[1][2]); acc[1][3]=fmaf(a1.y,b1v.w,acc[1][3]);
            acc[2][0]=fmaf(a2.y,b1v.x,acc[2][0]); acc[2][1]=fmaf(a2.y,b1v.y,acc[2][1]);
            acc[2][2]=fmaf(a2.y,b1v.z,acc[2][2]); acc[2][3]=fmaf(a2.y,b1v.w,acc[2][3]);
            acc[3][0]=fmaf(a3.y,b1v.x,acc[3][0]); acc[3][1]=fmaf(a3.y,b1v.y,acc[3][1]);
            acc[3][2]=fmaf(a3.y,b1v.z,acc[3][2]); acc[3][3]=fmaf(a3.y,b1v.w,acc[3][3]);
            // ii = 2
            acc[0][0]=fmaf(a0.z,b2v.x,acc[0][0]); acc[0][1]=fmaf(a0.z,b2v.y,acc[0][1]);
            acc[0][2]=fmaf(a0.z,b2v.z,acc[0][2]); acc[0][3]=fmaf(a0.z,b2v.w,acc[0][3]);
            acc[1][0]=fmaf(a1.z,b2v.x,acc[1][0]); acc[1][1]=fmaf(a1.z,b2v.y,acc[1][1]);
            acc[1][2]=fmaf(a1.z,b2v.z,acc[1][2]); acc[1][3]=fmaf(a1.z,b2v.w,acc[1][3]);
            acc[2][0]=fmaf(a2.z,b2v.x,acc[2][0]); acc[2][1]=fmaf(a2.z,b2v.y,acc[2][1]);
            acc[2][2]=fmaf(a2.z,b2v.z,acc[2][2]); acc[2][3]=fmaf(a2.z,b2v.w,acc[2][3]);
            acc[3][0]=fmaf(a3.z,b2v.x,acc[3][0]); acc[3][1]=fmaf(a3.z,b2v.y,acc[3][1]);
            acc[3][2]=fmaf(a3.z,b2v.z,acc[3][2]); acc[3][3]=fmaf(a3.z,b2v.w,acc[3][3]);
            // ii = 3
            acc[0][0]=fmaf(a0.w,b3v.x,acc[0][0]); acc[0][1]=fmaf(a0.w,b3v.y,acc[0][1]);
            acc[0][2]=fmaf(a0.w,b3v.z,acc[0][2]); acc[0][3]=fmaf(a0.w,b3v.w,acc[0][3]);
            acc[1][0]=fmaf(a1.w,b3v.x,acc[1][0]); acc[1][1]=fmaf(a1.w,b3v.y,acc[1][1]);
            acc[1][2]=fmaf(a1.w,b3v.z,acc[1][2]); acc[1][3]=fmaf(a1.w,b3v.w,acc[1][3]);
            acc[2][0]=fmaf(a2.w,b3v.x,acc[2][0]); acc[2][1]=fmaf(a2.w,b3v.y,acc[2][1]);
            acc[2][2]=fmaf(a2.w,b3v.z,acc[2][2]); acc[2][3]=fmaf(a2.w,b3v.w,acc[2][3]);
            acc[3][0]=fmaf(a3.w,b3v.x,acc[3][0]); acc[3][1]=fmaf(a3.w,b3v.y,acc[3][1]);
            acc[3][2]=fmaf(a3.w,b3v.z,acc[3][2]); acc[3][3]=fmaf(a3.w,b3v.w,acc[3][3]);
#undef ENC_STEP
        }
        // relu + partial mean over this thread's 4 k (ascending k order)
#pragma unroll
        for (int jj = 0; jj < 4; jj++) {
            float s = fmaxf(acc[0][jj], 0.f);
            s += fmaxf(acc[1][jj], 0.f);
            s += fmaxf(acc[2][jj], 0.f);
            s += fmaxf(acc[3][jj], 0.f);
            spart[kq][j0 + jj] = s;
        }
    }
    __syncthreads();
    if (t < 64)
        shbar[t] = (spart[0][t] + spart[1][t] + spart[2][t] + spart[3][t]) * 0.0625f;
    __syncthreads();

    if (t < 32) {
        float v = b3[t];
        for (int jj = 0; jj < 64; jj++) v = fmaf(shbar[jj], W3[jj*Dd + t], v);
        g_c0[(b*Mm + m)*Dd + t] = v;   // c_loc only
    }
}

// ---------------- CG: sheaf Laplacian edge pass (R tiles in smem) -----------
__device__ __forceinline__ void edge_pass(
    const float* __restrict__ sRS, const float* __restrict__ sRD,
    const float* __restrict__ sV, float* __restrict__ sGs, float* __restrict__ sGd,
    float* __restrict__ sRe, int nE, int wid, int lane)
{
    int rho = lane >> 1, h = lane & 1;
    int d = lane;
    for (int el = wid; el < nE; el += 32) {
        const float* bs = sRS + el*528;
        const float* bd = sRD + el*528;
        const float* ps = sV + el*32 + 16*h;     // src half; dst at +32
        const float* rs_ = bs + rho*33 + 16*h;
        const float* rd_ = bd + rho*33 + 16*h;
        float a0 = 0.f, a1 = 0.f, a2 = 0.f, a3 = 0.f;
#pragma unroll
        for (int i = 0; i < 16; i += 4) {
            a0 = fmaf(rs_[i+0], ps[i+0], a0);
            a1 = fmaf(rs_[i+1], ps[i+1], a1);
            a2 = fmaf(rs_[i+2], ps[i+2], a2);
            a3 = fmaf(rs_[i+3], ps[i+3], a3);
            a0 = fmaf(rd_[i+0], -ps[32+i+0], a0);
            a1 = fmaf(rd_[i+1], -ps[32+i+1], a1);
            a2 = fmaf(rd_[i+2], -ps[32+i+2], a2);
            a3 = fmaf(rd_[i+3], -ps[32+i+3], a3);
        }
        float acc = (a0 + a1) + (a2 + a3);
        acc += __shfl_xor_sync(0xffffffffu, acc, 1);
        if (h == 0) sRe[el*16 + rho] = acc;
        __syncwarp();

        float g0 = 0.f, g1 = 0.f, q0a = 0.f, q1a = 0.f;
#pragma unroll
        for (int q = 0; q < 16; q += 2) {
            float r0v = sRe[el*16 + q];
            float r1v = sRe[el*16 + q + 1];
            g0  = fmaf(bs[q*33 + d],       r0v, g0);
            g1  = fmaf(bs[(q+1)*33 + d],   r1v, g1);
            q0a = fmaf(bd[q*33 + d],       r0v, q0a);
            q1a = fmaf(bd[(q+1)*33 + d],   r1v, q1a);
        }
        sGs[el*32 + d] = g0 + g1;
        sGd[el*32 + d] = q0a + q1a;
    }
}

// ---------------- kernel 2: single-sync CG + fused gvec (8x8 cluster) -------
// smem layout (float offsets); nE <= 33, nExt <= 34
#define SM_RS   0                        // 33*528 = 17424
#define SM_RD   17424
#define SM_RV   34848                    // r extended, 34*32 = 1088
#define SM_W    (SM_RV + 1088)           // w own, 1024
#define SM_S    (SM_W + 1024)            // s extended, 1088
#define SM_PP   (SM_S + 1088)            // p own, 1024
#define SM_X    (SM_PP + 1024)           // x own, 1024
#define SM_GS   (SM_X + 1024)            // 33*32 = 1056
#define SM_GD   (SM_GS + 1056)           // 1056
#define SM_RE   (SM_GD + 1056)           // 33*16 = 528
#define SM_RED  (SM_RE + 528)            // 32 gamma + 32 delta warp partials
#define SM_SC   (SM_RED + 64)            // [par][g:8|d:8] = 32
#define SM_WH   (SM_SC + 32)             // [par][L:32|R:32] = 128
#define SM_GP   (SM_WH + 128)            // gvec grp partials 16*64 = 1024
#define SM_GVL  (SM_GP + 1024)           // local gvec partial [64]
#define SM_GV   (SM_GVL + 64)            // incoming partials [8][64] = 512
#define SM_SG   (SM_GV + 512)            // sg [64]
#define SM_GVEC (SM_SG + 64)             // gvec [32]
#define SM_TOT_FLOATS (SM_GVEC + 32)
#define SMEM_CG_BYTES (SM_TOT_FLOATS * 4)

__global__ __launch_bounds__(1024, 1) __cluster_dims__(8, 1, 1)
void cg_kernel(const float* __restrict__ Rsrc, const float* __restrict__ Rdst,
               const float* __restrict__ xs, const float* __restrict__ us,
               const float* __restrict__ Wg1, const float* __restrict__ bg1,
               const float* __restrict__ Wg2, const float* __restrict__ bg2,
               float* __restrict__ out)
{
    extern __shared__ float sm[];
    float* sRS  = sm + SM_RS;
    float* sRD  = sm + SM_RD;
    float* sRV  = sm + SM_RV;
    float* sW   = sm + SM_W;
    float* sS   = sm + SM_S;
    float* sPP  = sm + SM_PP;
    float* sX   = sm + SM_X;
    float* sGs  = sm + SM_GS;
    float* sGd  = sm + SM_GD;
    float* sRe  = sm + SM_RE;
    float* sRed = sm + SM_RED;

    int t = threadIdx.x, wid = t >> 5, lane = t & 31;
    int blk = blockIdx.x;
    int b = blk >> 3, c = blk & 7;          // cluster = batch, rank = c
    int m0 = c * 32;
    int mLo = (c > 0) ? m0 - 1 : 0;
    int eLo = (c > 0) ? m0 - 1 : 0;
    int eHi = (c < 7) ? m0 + 31 : 254;
    int nE = eHi - eLo + 1;                 // 32 or 33
    int nExt = 32 + (c > 0 ? 1 : 0) + (c < 7 ? 1 : 0);
    int ownOff = (c > 0) ? 32 : 0;
    int rhOff = ownOff + 1024;              // right-halo offset in extended bufs

    unsigned smb = smem_u32(sm);

    // ---- gvec partials: this CTA handles sensors [c*256, c*256+256) ----
    {
        int h = t & 63, grp = t >> 6;       // grp 0..15
        const float* xp = xs + b*Nn + c*256 + grp*16;
        const float* up = us + b*Nn + c*256 + grp*16;
        float w0 = __ldg(&Wg1[h]), w1 = __ldg(&Wg1[Hh+h]), bb = __ldg(&bg1[h]);
        float acc = 0.f;
#pragma unroll
        for (int j = 0; j < 16; j++)
            acc += fmaxf(fmaf(xp[j], w0, fmaf(up[j], w1, bb)), 0.f);
        sm[SM_GP + grp*64 + h] = acc;
    }
    __syncthreads();
    if (t < 64) {
        float s = 0.f;
#pragma unroll
        for (int g = 0; g < 16; g++) s += sm[SM_GP + g*64 + t];
        sm[SM_GVL + t] = s;
    }
    __syncthreads();
    if (t < 512) {                          // push my 64 partials to all ranks
        int rk = t >> 6, hh = t & 63;
        st_remote(smb + (SM_GV + c*64 + hh)*4, (unsigned)rk, sm[SM_GVL + hh]);
    }

    // ---- load R tiles into padded smem (overlaps with gvec exchange) ----
    for (int i = t; i < nE*512; i += 1024) {
        int el = i >> 9, rem = i & 511;
        int rho = rem >> 5, d = rem & 31;
        int g = (eLo + el)*512 + rem;
        sRS[el*528 + rho*33 + d] = Rsrc[g];
        sRD[el*528 + rho*33 + d] = Rdst[g];
    }
    // c_loc extended into sRV (gvec added after sync)
    const float* c0b = g_c0 + b*Mm*Dd;
    for (int i = t; i < nExt*32; i += 1024) sRV[i] = c0b[mLo*32 + i];
    cluster_sync_();

    // ---- finish gvec: reduce 8 rank partials, project to d ----
    if (t < 64) {
        float s = 0.f;
#pragma unroll
        for (int j = 0; j < 8; j++) s += sm[SM_GV + j*64 + t];
        sm[SM_SG + t] = s * (1.0f/Nn);
    }
    __syncthreads();
    if (t < 32) {
        float a = __ldg(&bg2[t]);
        for (int hh = 0; hh < Hh; hh++)
            a = fmaf(sm[SM_SG + hh], __ldg(&Wg2[hh*Dd + t]), a);
        sm[SM_GVEC + t] = a;
    }
    __syncthreads();
    for (int i = t; i < nExt*32; i += 1024) sRV[i] += sm[SM_GVEC + (i & 31)];
    __syncthreads();

    // ---- prologue: x = c0; write c0 out; r0 = -LAM*L(c0) ----
    edge_pass(sRS, sRD, sRV, sGs, sGd, sRe, nE, wid, lane);
    __syncthreads();
    {
        int dd = t & 31, m = m0 + (t >> 5);
        float gs = (m <= Mm-2) ? sGs[(m - eLo)*32 + dd] : 0.f;
        float gd = (m >= 1)    ? sGd[(m - 1 - eLo)*32 + dd] : 0.f;
        float c0v = sRV[ownOff + t];
        sX[t] = c0v;
        out[Bb*Qq + (b*Mm + m0)*32 + t] = c0v;   // c0 output segment
        sRV[ownOff + t] = -LAM * (gs - gd);      // r0 own
    }
    __syncthreads();
    // push r0 boundary rows into neighbors' WH parity-1 slots
    if (c > 0 && t < 32)
        st_remote(smb + (SM_WH + 64 + 32 + t)*4, (unsigned)(c-1), sRV[ownOff + t]);
    if (c < 7 && t >= 32 && t < 64) { int l = t - 32;
        st_remote(smb + (SM_WH + 64 + l)*4, (unsigned)(c+1), sRV[ownOff + 31*32 + l]); }
    cluster_sync_();
    if (c > 0 && t < 32)               sRV[t] = sm[SM_WH + 64 + t];
    if (c < 7 && t >= 32 && t < 64) {  int l = t - 32;
                                       sRV[rhOff + l] = sm[SM_WH + 64 + 32 + l]; }
    __syncthreads();

    float gamma_prev = 1.f, alpha_prev = 1.f;
    for (int k = 0; k < NITER; k++) {
        int par = k & 1;
        // ---- w = A r (own nodes); gamma = r.r, delta = r.w ----
        edge_pass(sRS, sRD, sRV, sGs, sGd, sRe, nE, wid, lane);
        __syncthreads();
        {
            int dd = t & 31, m = m0 + (t >> 5);
            float gs = (m <= Mm-2) ? sGs[(m - eLo)*32 + dd] : 0.f;
            float gd = (m >= 1)    ? sGd[(m - 1 - eLo)*32 + dd] : 0.f;
            float rv = sRV[ownOff + t];
            float wv = fmaf(LAM, gs - gd, rv);
            sW[t] = wv;
            float g = warp_sum(rv * rv);
            float d = warp_sum(rv * wv);
            if (lane == 0) { sRed[wid] = g; sRed[32 + wid] = d; }
        }
        __syncthreads();
        // ---- pushes: scalars (warp all-reduce) + w boundary rows ----
        if (wid == 0) {
            float tot = warp_sum(sRed[lane]);
            if (lane < 8) st_remote(smb + (SM_SC + par*16 + c)*4, (unsigned)lane, tot);
        } else if (wid == 1) {
            float tot = warp_sum(sRed[32 + lane]);
            if (lane < 8) st_remote(smb + (SM_SC + par*16 + 8 + c)*4, (unsigned)lane, tot);
        }
        if (c > 0 && t >= 64 && t < 96) { int l = t - 64;
            st_remote(smb + (SM_WH + par*64 + 32 + l)*4, (unsigned)(c-1), sW[l]); }
        if (c < 7 && t >= 96 && t < 128) { int l = t - 96;
            st_remote(smb + (SM_WH + par*64 + l)*4, (unsigned)(c+1), sW[31*32 + l]); }
        cluster_sync_();

        // ---- scalars (identical on all CTAs) ----
        float gamma = 0.f, delta = 0.f;
#pragma unroll
        for (int j = 0; j < 8; j++) { gamma += sm[SM_SC + par*16 + j];
                                      delta += sm[SM_SC + par*16 + 8 + j]; }
        float beta  = (k == 0) ? 0.f : gamma / (gamma_prev + 1e-12f);
        float den   = (k == 0) ? delta : delta - beta * gamma / alpha_prev;
        float alpha = gamma / (den + 1e-12f);

        // ---- local updates: s,r extended; p,x own ----
        for (int i = t; i < nExt*32; i += 1024) {
            int io = i - ownOff;
            float wv;
            if (io >= 0 && io < 1024)      wv = sW[io];
            else if (io < 0)               wv = sm[SM_WH + par*64 + i];
            else                           wv = sm[SM_WH + par*64 + 32 + (io - 1024)];
            float sv = (k == 0) ? wv : fmaf(beta, sS[i], wv);
            sS[i] = sv;
            if (io >= 0 && io < 1024) {
                float rold = sRV[i];
                float pv = (k == 0) ? rold : fmaf(beta, sPP[io], rold);
                sPP[io] = pv;
                sX[io] = fmaf(alpha, pv, sX[io]);
            }
            sRV[i] = fmaf(-alpha, sv, sRV[i]);
        }
        __syncthreads();

        gamma_prev = gamma;
        alpha_prev = alpha;
    }

    // final x -> g_c and out c segment
    {
        float v = sX[t];
        int o = (b*Mm + m0)*32 + t;
        g_c[o] = v;
        out[Bb*Qq + Bb*Mm*Dd + o] = v;
    }
}

// ---------------- kernel 3: sparse decode (16 thr/q, float2 loads) ----------
__global__ __launch_bounds__(256) void dec_kernel(
    const float* __restrict__ phi, const float* __restrict__ w,
    float* __restrict__ out)
{
    __shared__ float sc[3*8*32];
    __shared__ float sw[3*16];
    int blk = blockIdx.x, t = threadIdx.x;
    int q0 = blk * 16;
    int g = blk >> 2;                  // 64-q group shares an m-center
    int mlist[3] = {0, 0, 0};
    int nm = 0;
#pragma unroll
    for (int dm = -1; dm <= 1; dm++) {
        int mm = g + dm;
        if (mm >= 0 && mm < Mm) mlist[nm++] = mm;
    }
    for (int i = t; i < nm*256; i += 256) {
        int mi = i >> 8, rem = i & 255;
        int bidx = rem >> 5, d = rem & 31;
        sc[i] = g_c[(bidx*Mm + mlist[mi])*Dd + d];
    }
    if (t < nm*16) {
        int mi = t >> 4, ql = t & 15;
        sw[t] = w[mlist[mi]*Qq + q0 + ql];
    }
    __syncthreads();

    int ql = t >> 4, dq = t & 15;      // 16 threads per q, 2 d each
    int q = q0 + ql;

    // hoist all (up to 3) phi loads: independent, front-batched
    float2 pv[3];
    float wq[3];
#pragma unroll
    for (int mi = 0; mi < 3; mi++) {
        if (mi < nm) {
            pv[mi] = *(const float2*)(phi + ((size_t)mlist[mi]*Qq + q)*Dd + dq*2);
            wq[mi] = sw[mi*16 + ql];
        } else {
            pv[mi] = make_float2(0.f, 0.f);
            wq[mi] = 0.f;
        }
    }

    float s[8];
#pragma unroll
    for (int bidx = 0; bidx < 8; bidx++) s[bidx] = 0.f;

#pragma unroll
    for (int mi = 0; mi < 3; mi++) {
        int ms = (mi < nm) ? mi : 0;   // valid smem index; wq=0 kills the term
#pragma unroll
        for (int bidx = 0; bidx < 8; bidx++) {
            const float* cc = &sc[(ms*8 + bidx)*32 + dq*2];
            float dot = pv[mi].x*cc[0] + pv[mi].y*cc[1];
            s[bidx] = fmaf(wq[mi], dot, s[bidx]);
        }
    }
#pragma unroll
    for (int bidx = 0; bidx < 8; bidx++) {
        s[bidx] += __shfl_xor_sync(0xffffffffu, s[bidx], 1);
        s[bidx] += __shfl_xor_sync(0xffffffffu, s[bidx], 2);
        s[bidx] += __shfl_xor_sync(0xffffffffu, s[bidx], 4);
        s[bidx] += __shfl_xor_sync(0xffffffffu, s[bidx], 8);
    }
    if (dq == 0) {
#pragma unroll
        for (int bidx = 0; bidx < 8; bidx++)
            out[bidx*Qq + q] = s[bidx];
    }
}

// ---------------- launch ----------------------------------------------------
extern "C" void kernel_launch(void* const* d_in, const int* in_sizes, int n_in,
                              void* d_out, int out_size)
{
    (void)in_sizes; (void)n_in; (void)out_size;
    const float* xs      = (const float*)d_in[0];
    const float* us      = (const float*)d_in[1];
    const float* phi     = (const float*)d_in[2];
    const float* w       = (const float*)d_in[3];
    const float* centers = (const float*)d_in[4];
    const float* Rsrc    = (const float*)d_in[5];
    const float* Rdst    = (const float*)d_in[6];
    const float* W1      = (const float*)d_in[7];
    const float* b1      = (const float*)d_in[8];
    const float* W2      = (const float*)d_in[9];
    const float* b2      = (const float*)d_in[10];
    const float* W3      = (const float*)d_in[11];
    const float* b3      = (const float*)d_in[12];
    const float* Wg1     = (const float*)d_in[13];
    const float* bg1     = (const float*)d_in[14];
    const float* Wg2     = (const float*)d_in[15];
    const float* bg2     = (const float*)d_in[16];
    const int*   idx     = (const int*)d_in[17];
    float* out = (float*)d_out;

    cudaFuncSetAttribute(cg_kernel, cudaFuncAttributeMaxDynamicSharedMemorySize,
                         SMEM_CG_BYTES);

    enc_kernel<<<dim3(Mm, Bb), 64>>>(xs, us, centers, idx,
                                     W1, b1, W2, b2, W3, b3);
    cg_kernel<<<64, 1024, SMEM_CG_BYTES>>>(Rsrc, Rdst, xs, us,
                                           Wg1, bg1, Wg2, bg2, out);
    dec_kernel<<<Qq/16, 256>>>(phi, w, out);
}